// round 15
// baseline (speedup 1.0000x reference)
#include <cuda_runtime.h>
#include <cuda_bf16.h>
#include <cstdint>

#define N_NODES 100000
#define N_EDGES 1200000
#define HID 64

// ---------------- device scratch (no allocations allowed) ----------------
__device__ int   g_cnt[N_NODES];      // zero-initialized at load; re-zeroed by scan3
__device__ int   g_rowstart[N_NODES + 1];
__device__ int   g_cursor[N_NODES];
__device__ int   g_bsum[128];
__device__ int   g_boff[128];
__device__ int   g_esrc[N_EDGES];
__device__ float g_h[(size_t)N_NODES * HID];
__device__ float g_z[(size_t)N_NODES * HID];
__device__ float g_A[(size_t)N_NODES * HID];   // z @ Ws + cb1
__device__ float g_B[(size_t)N_NODES * HID];   // z @ Wd
__device__ int   g_is64;

// ---------------- helpers -------------------------------------------------
__device__ __forceinline__ void bf16_split(float v, float& hi, float& lo) {
    __nv_bfloat16 h = __float2bfloat16(v);
    hi = __bfloat162float(h);
    lo = v - hi;
}
__device__ __forceinline__ uint32_t pack2(float a, float b) {
    __nv_bfloat162 h = __floats2bfloat162_rn(a, b);
    return *(uint32_t*)&h;
}
// mma.sync m16n8k16 bf16 (A row-major frag, B col-major frag), f32 accum
__device__ __forceinline__ void hmma(float* d, const uint4 a, const uint2 b) {
    asm volatile("mma.sync.aligned.m16n8k16.row.col.f32.bf16.bf16.f32 "
        "{%0,%1,%2,%3}, {%4,%5,%6,%7}, {%8,%9}, {%0,%1,%2,%3};"
        : "+f"(d[0]), "+f"(d[1]), "+f"(d[2]), "+f"(d[3])
        : "r"(a.x), "r"(a.y), "r"(a.z), "r"(a.w), "r"(b.x), "r"(b.y));
}

// ---------------- dtype detection for edge_index (int64 vs int32) --------
__global__ void detect_kernel(const void* ei) {
    int lane = threadIdx.x;
    const long long* p = (const long long*)ei;
    int ok = 1;
    for (int i = lane; i < 256; i += 32) {
        long long v = p[i];
        if (v < 0 || v >= N_NODES) ok = 0;
    }
    ok = __all_sync(0xffffffffu, ok);
    if (lane == 0) g_is64 = ok;
}

__device__ __forceinline__ int load_idx(const void* ei, long long i, int is64) {
    if (is64) return (int)((const long long*)ei)[i];
    return ((const int*)ei)[i];
}

// ---------------- CSR build ----------------
__global__ void hist_kernel(const void* __restrict__ ei) {
    int is64 = g_is64;
    int e = blockIdx.x * blockDim.x + threadIdx.x;
    if (e < N_EDGES) {
        int dst = load_idx(ei, (long long)N_EDGES + e, is64);
        atomicAdd(&g_cnt[dst], 1);
    }
}

__global__ void scan1_kernel() {
    __shared__ int s[1024];
    int t = threadIdx.x;
    int i = blockIdx.x * 1024 + t;
    int v = (i < N_NODES) ? g_cnt[i] : 0;
    s[t] = v;
    __syncthreads();
    for (int off = 1; off < 1024; off <<= 1) {
        int u = (t >= off) ? s[t - off] : 0;
        __syncthreads();
        s[t] += u;
        __syncthreads();
    }
    if (i < N_NODES) g_rowstart[i] = s[t] - v;
    if (t == 1023) g_bsum[blockIdx.x] = s[1023];
}

__global__ void scan2_kernel(int nblocks) {
    __shared__ int s[128];
    int t = threadIdx.x;
    int v = (t < nblocks) ? g_bsum[t] : 0;
    s[t] = v;
    __syncthreads();
    for (int off = 1; off < 128; off <<= 1) {
        int u = (t >= off) ? s[t - off] : 0;
        __syncthreads();
        s[t] += u;
        __syncthreads();
    }
    g_boff[t] = s[t] - v;
}

// scan3 also re-zeroes g_cnt for the NEXT call (g_cnt consumed by scan1/scan2).
__global__ void scan3_kernel() {
    int i = blockIdx.x * blockDim.x + threadIdx.x;
    if (i < N_NODES) {
        int r = g_rowstart[i] + g_boff[i >> 10];
        g_rowstart[i] = r;
        g_cursor[i] = r;
        g_cnt[i] = 0;
    }
    if (i == 0) g_rowstart[N_NODES] = N_EDGES;
}

__global__ void fill_kernel(const void* __restrict__ ei) {
    int is64 = g_is64;
    int e = blockIdx.x * blockDim.x + threadIdx.x;
    if (e < N_EDGES) {
        int dst = load_idx(ei, (long long)N_EDGES + e, is64);
        int src = load_idx(ei, (long long)e, is64);
        int p = atomicAdd(&g_cursor[dst], 1);
        g_esrc[p] = src;
    }
}

// ---------------- SAGE layer: fused agg + GEMM + LN + ReLU ---------------
// round-13 proven (fixed float2 2-edge unroll)
__global__ void __launch_bounds__(128) sage_kernel(
    const float* __restrict__ x0, int layer,
    const float* __restrict__ wl, const float* __restrict__ wr,
    const float* __restrict__ bias, const float* __restrict__ lng,
    const float* __restrict__ lnb)
{
    __shared__ __align__(16) float wl_t[64 * 68];   // [feat][k]
    __shared__ __align__(16) float wr_t[64 * 68];
    __shared__ __align__(16) float nb[4 * 4 * 128]; // warp x node x (mean64|x64)
    __shared__ float b_s[64], g_s[64], bb_s[64];

    const float* xin = (layer == 0) ? x0 : g_h;
    float* xout = (layer == 0) ? g_h : g_z;

    int tid = threadIdx.x;
    for (int i = tid; i < 64 * 64; i += 128) {
        int k = i >> 6, f = i & 63;
        wl_t[f * 68 + k] = wl[i];
        wr_t[f * 68 + k] = wr[i];
    }
    if (tid < 64) { b_s[tid] = bias[tid]; g_s[tid] = lng[tid]; bb_s[tid] = lnb[tid]; }
    __syncthreads();

    int w = tid >> 5, lane = tid & 31;
    float* mynb = nb + w * 512;

    for (int base = blockIdx.x * 16; base < N_NODES; base += gridDim.x * 16) {
        int n0 = base + w * 4;

        #pragma unroll
        for (int t = 0; t < 4; t++) {
            int node = n0 + t;
            if (node < N_NODES) {
                int rs = g_rowstart[node], re = g_rowstart[node + 1];
                float a0 = 0.f, a1 = 0.f;   // features 2*lane, 2*lane+1
                int i = rs;
                for (; i + 2 <= re; i += 2) {
                    int s0 = g_esrc[i], s1 = g_esrc[i + 1];
                    float2 v0 = ((const float2*)(xin + (size_t)s0 * 64))[lane];
                    float2 v1 = ((const float2*)(xin + (size_t)s1 * 64))[lane];
                    a0 += v0.x + v1.x;
                    a1 += v0.y + v1.y;
                }
                if (i < re) {
                    int s0 = g_esrc[i];
                    float2 v0 = ((const float2*)(xin + (size_t)s0 * 64))[lane];
                    a0 += v0.x;
                    a1 += v0.y;
                }
                float inv = 1.f / (float)max(re - rs, 1);
                float2 mv; mv.x = a0 * inv; mv.y = a1 * inv;
                ((float2*)(mynb + t * 128))[lane] = mv;
                float2 xv = ((const float2*)(xin + (size_t)node * 64))[lane];
                ((float2*)(mynb + t * 128 + 64))[lane] = xv;
            } else {
                float2 zv; zv.x = 0.f; zv.y = 0.f;
                ((float2*)(mynb + t * 128))[lane] = zv;
                ((float2*)(mynb + t * 128 + 64))[lane] = zv;
            }
        }
        __syncwarp();

        float acc[4][2];
        #pragma unroll
        for (int t = 0; t < 4; t++) { acc[t][0] = b_s[lane]; acc[t][1] = b_s[lane + 32]; }
        #pragma unroll 4
        for (int k4 = 0; k4 < 16; k4++) {
            float4 u0 = *(const float4*)&wl_t[lane * 68 + k4 * 4];
            float4 u1 = *(const float4*)&wl_t[(lane + 32) * 68 + k4 * 4];
            float4 v0 = *(const float4*)&wr_t[lane * 68 + k4 * 4];
            float4 v1 = *(const float4*)&wr_t[(lane + 32) * 68 + k4 * 4];
            #pragma unroll
            for (int t = 0; t < 4; t++) {
                float4 m  = *(const float4*)&mynb[t * 128 + k4 * 4];
                float4 xv = *(const float4*)&mynb[t * 128 + 64 + k4 * 4];
                acc[t][0] += m.x * u0.x + m.y * u0.y + m.z * u0.z + m.w * u0.w
                           + xv.x * v0.x + xv.y * v0.y + xv.z * v0.z + xv.w * v0.w;
                acc[t][1] += m.x * u1.x + m.y * u1.y + m.z * u1.z + m.w * u1.w
                           + xv.x * v1.x + xv.y * v1.y + xv.z * v1.z + xv.w * v1.w;
            }
        }

        #pragma unroll
        for (int t = 0; t < 4; t++) {
            int node = n0 + t;
            if (node >= N_NODES) continue;
            float o0 = acc[t][0], o1 = acc[t][1];
            float ssum = o0 + o1;
            #pragma unroll
            for (int off = 16; off > 0; off >>= 1) ssum += __shfl_xor_sync(0xffffffffu, ssum, off);
            float mu = ssum * (1.f / 64.f);
            float d0 = o0 - mu, d1 = o1 - mu;
            float vsum = d0 * d0 + d1 * d1;
            #pragma unroll
            for (int off = 16; off > 0; off >>= 1) vsum += __shfl_xor_sync(0xffffffffu, vsum, off);
            float rstd = rsqrtf(vsum * (1.f / 64.f) + 1e-5f);
            float r0 = d0 * rstd * g_s[lane]      + bb_s[lane];
            float r1 = d1 * rstd * g_s[lane + 32] + bb_s[lane + 32];
            xout[(size_t)node * 64 + lane]      = fmaxf(r0, 0.f);
            xout[(size_t)node * 64 + lane + 32] = fmaxf(r1, 0.f);
        }
        __syncwarp();
    }
}

// ---------------- per-node precompute (round-7 proven) -------------------
__global__ void __launch_bounds__(128) node_pre_kernel(
    const float* __restrict__ cw1, const float* __restrict__ cb1)
{
    __shared__ __align__(16) float ws_t[64 * 68];
    __shared__ __align__(16) float wd_t[64 * 68];
    __shared__ __align__(16) float zb[4 * 4 * 64];
    __shared__ float cb_s[64];

    int tid = threadIdx.x;
    for (int i = tid; i < 64 * 64; i += 128) {
        int k = i >> 6, f = i & 63;
        ws_t[f * 68 + k] = cw1[i];
        wd_t[f * 68 + k] = cw1[64 * 64 + i];
    }
    if (tid < 64) cb_s[tid] = cb1[tid];
    __syncthreads();

    int w = tid >> 5, lane = tid & 31;
    float* myz = zb + w * 256;

    for (int base = blockIdx.x * 16; base < N_NODES; base += gridDim.x * 16) {
        int n0 = base + w * 4;
        #pragma unroll
        for (int t = 0; t < 4; t++) {
            int node = n0 + t;
            if (node < N_NODES) {
                const float* zp = g_z + (size_t)node * 64;
                myz[t * 64 + lane]      = zp[lane];
                myz[t * 64 + lane + 32] = zp[lane + 32];
            } else {
                myz[t * 64 + lane]      = 0.f;
                myz[t * 64 + lane + 32] = 0.f;
            }
        }
        __syncwarp();

        float a[4][2], b[4][2];
        #pragma unroll
        for (int t = 0; t < 4; t++) {
            a[t][0] = cb_s[lane]; a[t][1] = cb_s[lane + 32];
            b[t][0] = 0.f; b[t][1] = 0.f;
        }
        #pragma unroll 4
        for (int k4 = 0; k4 < 16; k4++) {
            float4 s0 = *(const float4*)&ws_t[lane * 68 + k4 * 4];
            float4 s1 = *(const float4*)&ws_t[(lane + 32) * 68 + k4 * 4];
            float4 d0 = *(const float4*)&wd_t[lane * 68 + k4 * 4];
            float4 d1 = *(const float4*)&wd_t[(lane + 32) * 68 + k4 * 4];
            #pragma unroll
            for (int t = 0; t < 4; t++) {
                float4 z = *(const float4*)&myz[t * 64 + k4 * 4];
                a[t][0] += z.x * s0.x + z.y * s0.y + z.z * s0.z + z.w * s0.w;
                a[t][1] += z.x * s1.x + z.y * s1.y + z.z * s1.z + z.w * s1.w;
                b[t][0] += z.x * d0.x + z.y * d0.y + z.z * d0.z + z.w * d0.w;
                b[t][1] += z.x * d1.x + z.y * d1.y + z.z * d1.z + z.w * d1.w;
            }
        }
        #pragma unroll
        for (int t = 0; t < 4; t++) {
            int node = n0 + t;
            if (node >= N_NODES) continue;
            g_A[(size_t)node * 64 + lane]      = a[t][0];
            g_A[(size_t)node * 64 + lane + 32] = a[t][1];
            g_B[(size_t)node * 64 + lane]      = b[t][0];
            g_B[(size_t)node * 64 + lane + 32] = b[t][1];
        }
        __syncwarp();
    }
}

// ================= Edge classifier via mma.sync bf16-split ================
// M_TILE=16, 128 threads (4 warps), 4 CTAs/SM; dedup'd weights;
// synchronous combined base gather (round-8 mechanism).
#define M_TILE 16
#define N_TILES (N_EDGES / M_TILE)   // 75000

#define OFF_A1   0                     // 1 rowgrp x 12 kstep x 512B = 6144
#define OFF_A2   6144                  // 1 x 8 x 512               = 4096
#define OFF_B1   10240                 // 8 nt x 12 ks x 256B       = 24576
#define OFF_B2   34816                 // 4 nt x 8 ks x 256B        = 8192
#define OFF_BASE 43008                 // 16 x 68 f32               = 4352
#define OFF_LOG  47360                 // 16 f32 (pad 128)
#define OFF_CB2  47488
#define OFF_CW3  47616
#define EDGE_SMEM_TOTAL 47744

__device__ __forceinline__ uint32_t a1_off(int r, int c2) {
    return (uint32_t)(((r >> 4) * 12 + (c2 >> 3)) << 9)
         + (((r & 7) * 4 + (c2 & 3)) << 4)
         + ((((r >> 3) & 1) + 2 * ((c2 >> 2) & 1)) << 2);
}
__device__ __forceinline__ uint32_t a2_off(int r, int c2) {
    return (uint32_t)(((r >> 4) * 8 + (c2 >> 3)) << 9)
         + (((r & 7) * 4 + (c2 & 3)) << 4)
         + ((((r >> 3) & 1) + 2 * ((c2 >> 2) & 1)) << 2);
}

__global__ void __launch_bounds__(128, 4) edge_mma_kernel(
    const void* __restrict__ ei, const float* __restrict__ ea,
    const float* __restrict__ cw1,
    const float* __restrict__ cw2, const float* __restrict__ cb2,
    const float* __restrict__ cw3, const float* __restrict__ cb3,
    float* __restrict__ out)
{
    extern __shared__ char smem[];
    float* base_s = (float*)(smem + OFF_BASE);
    float* log_s  = (float*)(smem + OFF_LOG);
    float* cb2s   = (float*)(smem + OFF_CB2);
    float* cw3s   = (float*)(smem + OFF_CW3);

    const int tid = threadIdx.x;
    const int wid = tid >> 5, lane = tid & 31;
    const int q = lane & 3;

    // ---- weight prologue: B1 12 regions (hi 0..5, lo 6..11) — dedup ----
    for (int i = tid; i < 8 * 12 * 64; i += 128) {
        int nt = i / (12 * 64);
        int rem = i % (12 * 64);
        int ks = rem >> 6;
        int j = rem & 63;
        int ln = j >> 1, rg = j & 1;
        int n = nt * 8 + (ln >> 2);
        int kl = (ks % 6) * 16 + 2 * (ln & 3) + 8 * rg;   // [0,96)
        float w0 = cw1[(128 + kl) * 64 + n];
        float w1 = cw1[(128 + kl + 1) * 64 + n];
        float h0, l0, h1, l1;
        bf16_split(w0, h0, l0); bf16_split(w1, h1, l1);
        uint32_t v = (ks < 6) ? pack2(h0, h1) : pack2(l0, l1);
        *(uint32_t*)(smem + OFF_B1 + ((nt * 12 + ks) << 8) + ln * 8 + rg * 4) = v;
    }
    // ---- B2 8 regions (hi 0..3, lo 4..7) — dedup ----
    for (int i = tid; i < 4 * 8 * 64; i += 128) {
        int nt = i / (8 * 64);
        int rem = i % (8 * 64);
        int ks = rem >> 6;
        int j = rem & 63;
        int ln = j >> 1, rg = j & 1;
        int n = nt * 8 + (ln >> 2);
        int kl = (ks % 4) * 16 + 2 * (ln & 3) + 8 * rg;   // [0,64)
        float w0 = cw2[kl * 32 + n];
        float w1 = cw2[(kl + 1) * 32 + n];
        float h0, l0, h1, l1;
        bf16_split(w0, h0, l0); bf16_split(w1, h1, l1);
        uint32_t v = (ks < 4) ? pack2(h0, h1) : pack2(l0, l1);
        *(uint32_t*)(smem + OFF_B2 + ((nt * 8 + ks) << 8) + ln * 8 + rg * 4) = v;
    }
    if (tid < 32) { cb2s[tid] = cb2[tid]; cw3s[tid] = cw3[tid]; }
    if (tid < 16) log_s[tid] = 0.f;
    __syncthreads();

    const int is64 = g_is64;
    const float cb3v = cb3[0];
    // 4 warps: all rowgrp 0; warp covers 16 N-cols in L1, 8 in L2

    for (int tile = blockIdx.x; tile < N_TILES; tile += gridDim.x) {
        const int e0 = tile * M_TILE;

        // ---------------- gather: 4 warps x 4 edges ----------------
        #pragma unroll
        for (int t = 0; t < 4; t++) {
            int r = wid * 4 + t;          // 0..15
            int e = e0 + r;
            int src = load_idx(ei, (long long)e, is64);
            int dst = load_idx(ei, (long long)N_EDGES + e, is64);
            float2 a = ((const float2*)(g_z + (size_t)src * 64))[lane];
            float2 b = ((const float2*)(g_z + (size_t)dst * 64))[lane];
            float px = a.x * b.x, py = a.y * b.y;
            float hx, lx, hy, ly;
            bf16_split(px, hx, lx); bf16_split(py, hy, ly);
            *(uint32_t*)(smem + OFF_A1 + a1_off(r, lane))      = pack2(hx, hy);
            *(uint32_t*)(smem + OFF_A1 + a1_off(r, lane + 48)) = pack2(lx, ly);
            if (lane < 16) {
                float2 e2 = ((const float2*)(ea + (size_t)e * 32))[lane];
                float eh0, el0, eh1, el1;
                bf16_split(e2.x, eh0, el0); bf16_split(e2.y, eh1, el1);
                *(uint32_t*)(smem + OFF_A1 + a1_off(r, 32 + lane)) = pack2(eh0, eh1);
                *(uint32_t*)(smem + OFF_A1 + a1_off(r, 80 + lane)) = pack2(el0, el1);
            }
            float2 av = ((const float2*)(g_A + (size_t)src * 64))[lane];
            float2 bv = ((const float2*)(g_B + (size_t)dst * 64))[lane];
            base_s[r * 68 + 2 * lane]     = av.x + bv.x;
            base_s[r * 68 + 2 * lane + 1] = av.y + bv.y;
        }
        __syncthreads();

        // ---------------- L1 GEMM: 16 rows x 16 cols per warp ----------------
        float d[2][4] = {};
        #pragma unroll
        for (int s = 0; s < 18; s++) {
            int aks = (s < 12) ? s : s - 12;
            int bks = (s < 6) ? s : s - 6;
            uint4 A = *(const uint4*)(smem + OFF_A1 + (aks << 9) + lane * 16);
            #pragma unroll
            for (int nt = 0; nt < 2; nt++) {
                int ntg = wid * 2 + nt;
                uint2 B = *(const uint2*)(smem + OFF_B1 + ((ntg * 12 + bks) << 8) + lane * 8);
                hmma(d[nt], A, B);
            }
        }

        // ---------------- epilogue 1: +base, relu, split -> A2 ----------------
        {
            int r0 = lane >> 2;          // 0..7, rows r0 and r0+8
            #pragma unroll
            for (int nt = 0; nt < 2; nt++) {
                int c0 = wid * 16 + nt * 8 + 2 * q;
                float v00 = fmaxf(d[nt][0] + base_s[r0 * 68 + c0], 0.f);
                float v01 = fmaxf(d[nt][1] + base_s[r0 * 68 + c0 + 1], 0.f);
                float v10 = fmaxf(d[nt][2] + base_s[(r0 + 8) * 68 + c0], 0.f);
                float v11 = fmaxf(d[nt][3] + base_s[(r0 + 8) * 68 + c0 + 1], 0.f);
                float h00, l00, h01, l01, h10, l10, h11, l11;
                bf16_split(v00, h00, l00); bf16_split(v01, h01, l01);
                bf16_split(v10, h10, l10); bf16_split(v11, h11, l11);
                int c2 = c0 >> 1;
                *(uint32_t*)(smem + OFF_A2 + a2_off(r0,     c2))      = pack2(h00, h01);
                *(uint32_t*)(smem + OFF_A2 + a2_off(r0 + 8, c2))      = pack2(h10, h11);
                *(uint32_t*)(smem + OFF_A2 + a2_off(r0,     c2 + 32)) = pack2(l00, l01);
                *(uint32_t*)(smem + OFF_A2 + a2_off(r0 + 8, c2 + 32)) = pack2(l10, l11);
            }
        }
        __syncthreads();

        // ---------------- L2 GEMM: 16 rows x 8 cols per warp ----------------
        float e2a[4] = {};
        #pragma unroll
        for (int s = 0; s < 12; s++) {
            int aks = (s < 8) ? s : s - 8;
            int bks = (s < 4) ? s : s - 4;
            uint4 A = *(const uint4*)(smem + OFF_A2 + (aks << 9) + lane * 16);
            uint2 B = *(const uint2*)(smem + OFF_B2 + ((wid * 8 + bks) << 8) + lane * 8);
            hmma(e2a, A, B);
        }

        // ---------------- epilogue 2: +cb2, relu, dot cw3, reduce ------------
        {
            int c0 = wid * 8 + 2 * q;
            float w0 = cw3s[c0], w1 = cw3s[c0 + 1];
            float b0 = cb2s[c0], b1 = cb2s[c0 + 1];
            float p0 = fmaxf(e2a[0] + b0, 0.f) * w0 + fmaxf(e2a[1] + b1, 0.f) * w1;
            float p1 = fmaxf(e2a[2] + b0, 0.f) * w0 + fmaxf(e2a[3] + b1, 0.f) * w1;
            p0 += __shfl_xor_sync(0xffffffffu, p0, 1);
            p0 += __shfl_xor_sync(0xffffffffu, p0, 2);
            p1 += __shfl_xor_sync(0xffffffffu, p1, 1);
            p1 += __shfl_xor_sync(0xffffffffu, p1, 2);
            if (q == 0) {
                int r0 = lane >> 2;
                atomicAdd(&log_s[r0], p0);
                atomicAdd(&log_s[r0 + 8], p1);
            }
        }
        __syncthreads();

        if (tid < 16) {
            out[e0 + tid] = log_s[tid] + cb3v;
            log_s[tid] = 0.f;
        }
    }
}

// ---------------- launch ----------------
extern "C" void kernel_launch(void* const* d_in, const int* in_sizes, int n_in,
                              void* d_out, int out_size)
{
    const float* x   = (const float*)d_in[0];
    const void*  ei  = (const void*)d_in[1];
    const float* ea  = (const float*)d_in[2];
    const float* wl0 = (const float*)d_in[3];
    const float* wr0 = (const float*)d_in[4];
    const float* b0  = (const float*)d_in[5];
    const float* g0  = (const float*)d_in[6];
    const float* bb0 = (const float*)d_in[7];
    const float* wl1 = (const float*)d_in[8];
    const float* wr1 = (const float*)d_in[9];
    const float* b1  = (const float*)d_in[10];
    const float* g1  = (const float*)d_in[11];
    const float* bb1 = (const float*)d_in[12];
    const float* cw1 = (const float*)d_in[13];
    const float* cb1 = (const float*)d_in[14];
    const float* cw2 = (const float*)d_in[15];
    const float* cb2 = (const float*)d_in[16];
    const float* cw3 = (const float*)d_in[17];
    const float* cb3 = (const float*)d_in[18];
    float* out = (float*)d_out;

    const int SCAN_BLOCKS = (N_NODES + 1023) / 1024;  // 98

    detect_kernel<<<1, 32>>>(ei);
    hist_kernel<<<(N_EDGES + 255) / 256, 256>>>(ei);
    scan1_kernel<<<SCAN_BLOCKS, 1024>>>();
    scan2_kernel<<<1, 128>>>(SCAN_BLOCKS);
    scan3_kernel<<<(N_NODES + 255) / 256, 256>>>();
    fill_kernel<<<(N_EDGES + 255) / 256, 256>>>(ei);

    sage_kernel<<<1480, 128>>>(x, 0, wl0, wr0, b0, g0, bb0);
    sage_kernel<<<1480, 128>>>(x, 1, wl1, wr1, b1, g1, bb1);
    node_pre_kernel<<<1480, 128>>>(cw1, cb1);

    cudaFuncSetAttribute(edge_mma_kernel,
                         cudaFuncAttributeMaxDynamicSharedMemorySize, EDGE_SMEM_TOTAL);
    edge_mma_kernel<<<592, 128, EDGE_SMEM_TOTAL>>>(
        ei, ea, cw1, cw2, cb2, cw3, cb3, out);
}

// round 16
// speedup vs baseline: 1.0133x; 1.0133x over previous
#include <cuda_runtime.h>
#include <cuda_bf16.h>
#include <cstdint>

#define N_NODES 100000
#define N_EDGES 1200000
#define HID 64

// ---------------- device scratch (no allocations allowed) ----------------
__device__ int   g_cnt[N_NODES];      // zero-initialized at load; re-zeroed by scan3
__device__ int   g_rowstart[N_NODES + 1];
__device__ int   g_cursor[N_NODES];
__device__ int   g_bsum[128];
__device__ int   g_boff[128];
__device__ int   g_esrc[N_EDGES];
__device__ float g_h[(size_t)N_NODES * HID];
__device__ float g_z[(size_t)N_NODES * HID];
__device__ float g_A[(size_t)N_NODES * HID];   // z @ Ws + cb1
__device__ float g_B[(size_t)N_NODES * HID];   // z @ Wd
__device__ int   g_is64;

// ---------------- helpers -------------------------------------------------
__device__ __forceinline__ void bf16_split(float v, float& hi, float& lo) {
    __nv_bfloat16 h = __float2bfloat16(v);
    hi = __bfloat162float(h);
    lo = v - hi;
}
__device__ __forceinline__ uint32_t pack2(float a, float b) {
    __nv_bfloat162 h = __floats2bfloat162_rn(a, b);
    return *(uint32_t*)&h;
}
// mma.sync m16n8k16 bf16 (A row-major frag, B col-major frag), f32 accum
__device__ __forceinline__ void hmma(float* d, const uint4 a, const uint2 b) {
    asm volatile("mma.sync.aligned.m16n8k16.row.col.f32.bf16.bf16.f32 "
        "{%0,%1,%2,%3}, {%4,%5,%6,%7}, {%8,%9}, {%0,%1,%2,%3};"
        : "+f"(d[0]), "+f"(d[1]), "+f"(d[2]), "+f"(d[3])
        : "r"(a.x), "r"(a.y), "r"(a.z), "r"(a.w), "r"(b.x), "r"(b.y));
}

// ---------------- dtype detection for edge_index (int64 vs int32) --------
__global__ void detect_kernel(const void* ei) {
    int lane = threadIdx.x;
    const long long* p = (const long long*)ei;
    int ok = 1;
    for (int i = lane; i < 256; i += 32) {
        long long v = p[i];
        if (v < 0 || v >= N_NODES) ok = 0;
    }
    ok = __all_sync(0xffffffffu, ok);
    if (lane == 0) g_is64 = ok;
}

__device__ __forceinline__ int load_idx(const void* ei, long long i, int is64) {
    if (is64) return (int)((const long long*)ei)[i];
    return ((const int*)ei)[i];
}

// ---------------- CSR build ----------------
__global__ void hist_kernel(const void* __restrict__ ei) {
    int is64 = g_is64;
    int e = blockIdx.x * blockDim.x + threadIdx.x;
    if (e < N_EDGES) {
        int dst = load_idx(ei, (long long)N_EDGES + e, is64);
        atomicAdd(&g_cnt[dst], 1);
    }
}

__global__ void scan1_kernel() {
    __shared__ int s[1024];
    int t = threadIdx.x;
    int i = blockIdx.x * 1024 + t;
    int v = (i < N_NODES) ? g_cnt[i] : 0;
    s[t] = v;
    __syncthreads();
    for (int off = 1; off < 1024; off <<= 1) {
        int u = (t >= off) ? s[t - off] : 0;
        __syncthreads();
        s[t] += u;
        __syncthreads();
    }
    if (i < N_NODES) g_rowstart[i] = s[t] - v;
    if (t == 1023) g_bsum[blockIdx.x] = s[1023];
}

__global__ void scan2_kernel(int nblocks) {
    __shared__ int s[128];
    int t = threadIdx.x;
    int v = (t < nblocks) ? g_bsum[t] : 0;
    s[t] = v;
    __syncthreads();
    for (int off = 1; off < 128; off <<= 1) {
        int u = (t >= off) ? s[t - off] : 0;
        __syncthreads();
        s[t] += u;
        __syncthreads();
    }
    g_boff[t] = s[t] - v;
}

// scan3 also re-zeroes g_cnt for the NEXT call (g_cnt consumed by scan1/scan2).
__global__ void scan3_kernel() {
    int i = blockIdx.x * blockDim.x + threadIdx.x;
    if (i < N_NODES) {
        int r = g_rowstart[i] + g_boff[i >> 10];
        g_rowstart[i] = r;
        g_cursor[i] = r;
        g_cnt[i] = 0;
    }
    if (i == 0) g_rowstart[N_NODES] = N_EDGES;
}

__global__ void fill_kernel(const void* __restrict__ ei) {
    int is64 = g_is64;
    int e = blockIdx.x * blockDim.x + threadIdx.x;
    if (e < N_EDGES) {
        int dst = load_idx(ei, (long long)N_EDGES + e, is64);
        int src = load_idx(ei, (long long)e, is64);
        int p = atomicAdd(&g_cursor[dst], 1);
        g_esrc[p] = src;
    }
}

// ---------------- SAGE layer: fused agg + GEMM + LN + ReLU ---------------
// round-13/14 proven (fixed float2 2-edge unroll)
__global__ void __launch_bounds__(128) sage_kernel(
    const float* __restrict__ x0, int layer,
    const float* __restrict__ wl, const float* __restrict__ wr,
    const float* __restrict__ bias, const float* __restrict__ lng,
    const float* __restrict__ lnb)
{
    __shared__ __align__(16) float wl_t[64 * 68];   // [feat][k]
    __shared__ __align__(16) float wr_t[64 * 68];
    __shared__ __align__(16) float nb[4 * 4 * 128]; // warp x node x (mean64|x64)
    __shared__ float b_s[64], g_s[64], bb_s[64];

    const float* xin = (layer == 0) ? x0 : g_h;
    float* xout = (layer == 0) ? g_h : g_z;

    int tid = threadIdx.x;
    for (int i = tid; i < 64 * 64; i += 128) {
        int k = i >> 6, f = i & 63;
        wl_t[f * 68 + k] = wl[i];
        wr_t[f * 68 + k] = wr[i];
    }
    if (tid < 64) { b_s[tid] = bias[tid]; g_s[tid] = lng[tid]; bb_s[tid] = lnb[tid]; }
    __syncthreads();

    int w = tid >> 5, lane = tid & 31;
    float* mynb = nb + w * 512;

    for (int base = blockIdx.x * 16; base < N_NODES; base += gridDim.x * 16) {
        int n0 = base + w * 4;

        #pragma unroll
        for (int t = 0; t < 4; t++) {
            int node = n0 + t;
            if (node < N_NODES) {
                int rs = g_rowstart[node], re = g_rowstart[node + 1];
                float a0 = 0.f, a1 = 0.f;   // features 2*lane, 2*lane+1
                int i = rs;
                for (; i + 2 <= re; i += 2) {
                    int s0 = g_esrc[i], s1 = g_esrc[i + 1];
                    float2 v0 = ((const float2*)(xin + (size_t)s0 * 64))[lane];
                    float2 v1 = ((const float2*)(xin + (size_t)s1 * 64))[lane];
                    a0 += v0.x + v1.x;
                    a1 += v0.y + v1.y;
                }
                if (i < re) {
                    int s0 = g_esrc[i];
                    float2 v0 = ((const float2*)(xin + (size_t)s0 * 64))[lane];
                    a0 += v0.x;
                    a1 += v0.y;
                }
                float inv = 1.f / (float)max(re - rs, 1);
                float2 mv; mv.x = a0 * inv; mv.y = a1 * inv;
                ((float2*)(mynb + t * 128))[lane] = mv;
                float2 xv = ((const float2*)(xin + (size_t)node * 64))[lane];
                ((float2*)(mynb + t * 128 + 64))[lane] = xv;
            } else {
                float2 zv; zv.x = 0.f; zv.y = 0.f;
                ((float2*)(mynb + t * 128))[lane] = zv;
                ((float2*)(mynb + t * 128 + 64))[lane] = zv;
            }
        }
        __syncwarp();

        float acc[4][2];
        #pragma unroll
        for (int t = 0; t < 4; t++) { acc[t][0] = b_s[lane]; acc[t][1] = b_s[lane + 32]; }
        #pragma unroll 4
        for (int k4 = 0; k4 < 16; k4++) {
            float4 u0 = *(const float4*)&wl_t[lane * 68 + k4 * 4];
            float4 u1 = *(const float4*)&wl_t[(lane + 32) * 68 + k4 * 4];
            float4 v0 = *(const float4*)&wr_t[lane * 68 + k4 * 4];
            float4 v1 = *(const float4*)&wr_t[(lane + 32) * 68 + k4 * 4];
            #pragma unroll
            for (int t = 0; t < 4; t++) {
                float4 m  = *(const float4*)&mynb[t * 128 + k4 * 4];
                float4 xv = *(const float4*)&mynb[t * 128 + 64 + k4 * 4];
                acc[t][0] += m.x * u0.x + m.y * u0.y + m.z * u0.z + m.w * u0.w
                           + xv.x * v0.x + xv.y * v0.y + xv.z * v0.z + xv.w * v0.w;
                acc[t][1] += m.x * u1.x + m.y * u1.y + m.z * u1.z + m.w * u1.w
                           + xv.x * v1.x + xv.y * v1.y + xv.z * v1.z + xv.w * v1.w;
            }
        }

        #pragma unroll
        for (int t = 0; t < 4; t++) {
            int node = n0 + t;
            if (node >= N_NODES) continue;
            float o0 = acc[t][0], o1 = acc[t][1];
            float ssum = o0 + o1;
            #pragma unroll
            for (int off = 16; off > 0; off >>= 1) ssum += __shfl_xor_sync(0xffffffffu, ssum, off);
            float mu = ssum * (1.f / 64.f);
            float d0 = o0 - mu, d1 = o1 - mu;
            float vsum = d0 * d0 + d1 * d1;
            #pragma unroll
            for (int off = 16; off > 0; off >>= 1) vsum += __shfl_xor_sync(0xffffffffu, vsum, off);
            float rstd = rsqrtf(vsum * (1.f / 64.f) + 1e-5f);
            float r0 = d0 * rstd * g_s[lane]      + bb_s[lane];
            float r1 = d1 * rstd * g_s[lane + 32] + bb_s[lane + 32];
            xout[(size_t)node * 64 + lane]      = fmaxf(r0, 0.f);
            xout[(size_t)node * 64 + lane + 32] = fmaxf(r1, 0.f);
        }
        __syncwarp();
    }
}

// ---------------- per-node precompute (round-7 proven) -------------------
__global__ void __launch_bounds__(128) node_pre_kernel(
    const float* __restrict__ cw1, const float* __restrict__ cb1)
{
    __shared__ __align__(16) float ws_t[64 * 68];
    __shared__ __align__(16) float wd_t[64 * 68];
    __shared__ __align__(16) float zb[4 * 4 * 64];
    __shared__ float cb_s[64];

    int tid = threadIdx.x;
    for (int i = tid; i < 64 * 64; i += 128) {
        int k = i >> 6, f = i & 63;
        ws_t[f * 68 + k] = cw1[i];
        wd_t[f * 68 + k] = cw1[64 * 64 + i];
    }
    if (tid < 64) cb_s[tid] = cb1[tid];
    __syncthreads();

    int w = tid >> 5, lane = tid & 31;
    float* myz = zb + w * 256;

    for (int base = blockIdx.x * 16; base < N_NODES; base += gridDim.x * 16) {
        int n0 = base + w * 4;
        #pragma unroll
        for (int t = 0; t < 4; t++) {
            int node = n0 + t;
            if (node < N_NODES) {
                const float* zp = g_z + (size_t)node * 64;
                myz[t * 64 + lane]      = zp[lane];
                myz[t * 64 + lane + 32] = zp[lane + 32];
            } else {
                myz[t * 64 + lane]      = 0.f;
                myz[t * 64 + lane + 32] = 0.f;
            }
        }
        __syncwarp();

        float a[4][2], b[4][2];
        #pragma unroll
        for (int t = 0; t < 4; t++) {
            a[t][0] = cb_s[lane]; a[t][1] = cb_s[lane + 32];
            b[t][0] = 0.f; b[t][1] = 0.f;
        }
        #pragma unroll 4
        for (int k4 = 0; k4 < 16; k4++) {
            float4 s0 = *(const float4*)&ws_t[lane * 68 + k4 * 4];
            float4 s1 = *(const float4*)&ws_t[(lane + 32) * 68 + k4 * 4];
            float4 d0 = *(const float4*)&wd_t[lane * 68 + k4 * 4];
            float4 d1 = *(const float4*)&wd_t[(lane + 32) * 68 + k4 * 4];
            #pragma unroll
            for (int t = 0; t < 4; t++) {
                float4 z = *(const float4*)&myz[t * 64 + k4 * 4];
                a[t][0] += z.x * s0.x + z.y * s0.y + z.z * s0.z + z.w * s0.w;
                a[t][1] += z.x * s1.x + z.y * s1.y + z.z * s1.z + z.w * s1.w;
                b[t][0] += z.x * d0.x + z.y * d0.y + z.z * d0.z + z.w * d0.w;
                b[t][1] += z.x * d1.x + z.y * d1.y + z.z * d1.z + z.w * d1.w;
            }
        }
        #pragma unroll
        for (int t = 0; t < 4; t++) {
            int node = n0 + t;
            if (node >= N_NODES) continue;
            g_A[(size_t)node * 64 + lane]      = a[t][0];
            g_A[(size_t)node * 64 + lane + 32] = a[t][1];
            g_B[(size_t)node * 64 + lane]      = b[t][0];
            g_B[(size_t)node * 64 + lane + 32] = b[t][1];
        }
        __syncwarp();
    }
}

// ================= Edge classifier via mma.sync bf16-split ================
// ROUND-14 PROVEN OPTIMUM: M_TILE=32, 256 threads (8 warps), 3 CTAs/SM;
// dedup'd weights; synchronous combined base gather.
#define M_TILE 32
#define N_TILES (N_EDGES / M_TILE)   // 37500

#define OFF_A1   0                     // 2 rowgrp x 12 kstep x 512B = 12288
#define OFF_A2   12288                 // 2 x 8 x 512               = 8192
#define OFF_B1   20480                 // 8 nt x 12 ks x 256B       = 24576
#define OFF_B2   45056                 // 4 nt x 8 ks x 256B        = 8192
#define OFF_BASE 53248                 // 32 x 68 f32               = 8704
#define OFF_LOG  61952                 // 32 f32 (pad 128)
#define OFF_CB2  62080
#define OFF_CW3  62208
#define EDGE_SMEM_TOTAL 62336

__device__ __forceinline__ uint32_t a1_off(int r, int c2) {
    return (uint32_t)(((r >> 4) * 12 + (c2 >> 3)) << 9)
         + (((r & 7) * 4 + (c2 & 3)) << 4)
         + ((((r >> 3) & 1) + 2 * ((c2 >> 2) & 1)) << 2);
}
__device__ __forceinline__ uint32_t a2_off(int r, int c2) {
    return (uint32_t)(((r >> 4) * 8 + (c2 >> 3)) << 9)
         + (((r & 7) * 4 + (c2 & 3)) << 4)
         + ((((r >> 3) & 1) + 2 * ((c2 >> 2) & 1)) << 2);
}

__global__ void __launch_bounds__(256, 3) edge_mma_kernel(
    const void* __restrict__ ei, const float* __restrict__ ea,
    const float* __restrict__ cw1,
    const float* __restrict__ cw2, const float* __restrict__ cb2,
    const float* __restrict__ cw3, const float* __restrict__ cb3,
    float* __restrict__ out)
{
    extern __shared__ char smem[];
    float* base_s = (float*)(smem + OFF_BASE);
    float* log_s  = (float*)(smem + OFF_LOG);
    float* cb2s   = (float*)(smem + OFF_CB2);
    float* cw3s   = (float*)(smem + OFF_CW3);

    const int tid = threadIdx.x;
    const int wid = tid >> 5, lane = tid & 31;
    const int q = lane & 3;

    // ---- weight prologue: B1 12 regions (hi 0..5, lo 6..11) — dedup ----
    for (int i = tid; i < 8 * 12 * 64; i += 256) {
        int nt = i / (12 * 64);
        int rem = i % (12 * 64);
        int ks = rem >> 6;
        int j = rem & 63;
        int ln = j >> 1, rg = j & 1;
        int n = nt * 8 + (ln >> 2);
        int kl = (ks % 6) * 16 + 2 * (ln & 3) + 8 * rg;   // [0,96)
        float w0 = cw1[(128 + kl) * 64 + n];
        float w1 = cw1[(128 + kl + 1) * 64 + n];
        float h0, l0, h1, l1;
        bf16_split(w0, h0, l0); bf16_split(w1, h1, l1);
        uint32_t v = (ks < 6) ? pack2(h0, h1) : pack2(l0, l1);
        *(uint32_t*)(smem + OFF_B1 + ((nt * 12 + ks) << 8) + ln * 8 + rg * 4) = v;
    }
    // ---- B2 8 regions (hi 0..3, lo 4..7) — dedup ----
    for (int i = tid; i < 4 * 8 * 64; i += 256) {
        int nt = i / (8 * 64);
        int rem = i % (8 * 64);
        int ks = rem >> 6;
        int j = rem & 63;
        int ln = j >> 1, rg = j & 1;
        int n = nt * 8 + (ln >> 2);
        int kl = (ks % 4) * 16 + 2 * (ln & 3) + 8 * rg;   // [0,64)
        float w0 = cw2[kl * 32 + n];
        float w1 = cw2[(kl + 1) * 32 + n];
        float h0, l0, h1, l1;
        bf16_split(w0, h0, l0); bf16_split(w1, h1, l1);
        uint32_t v = (ks < 4) ? pack2(h0, h1) : pack2(l0, l1);
        *(uint32_t*)(smem + OFF_B2 + ((nt * 8 + ks) << 8) + ln * 8 + rg * 4) = v;
    }
    if (tid < 32) { cb2s[tid] = cb2[tid]; cw3s[tid] = cw3[tid]; log_s[tid] = 0.f; }
    __syncthreads();

    const int is64 = g_is64;
    const float cb3v = cb3[0];
    const int rowgrp = wid & 1, npair = wid >> 1;   // npair in [0,4)

    for (int tile = blockIdx.x; tile < N_TILES; tile += gridDim.x) {
        const int e0 = tile * M_TILE;

        // ---------------- gather: 8 warps x 4 edges ----------------
        #pragma unroll
        for (int t = 0; t < 4; t++) {
            int r = wid * 4 + t;          // 0..31
            int e = e0 + r;
            int src = load_idx(ei, (long long)e, is64);
            int dst = load_idx(ei, (long long)N_EDGES + e, is64);
            float2 a = ((const float2*)(g_z + (size_t)src * 64))[lane];
            float2 b = ((const float2*)(g_z + (size_t)dst * 64))[lane];
            float px = a.x * b.x, py = a.y * b.y;
            float hx, lx, hy, ly;
            bf16_split(px, hx, lx); bf16_split(py, hy, ly);
            *(uint32_t*)(smem + OFF_A1 + a1_off(r, lane))      = pack2(hx, hy);
            *(uint32_t*)(smem + OFF_A1 + a1_off(r, lane + 48)) = pack2(lx, ly);
            if (lane < 16) {
                float2 e2 = ((const float2*)(ea + (size_t)e * 32))[lane];
                float eh0, el0, eh1, el1;
                bf16_split(e2.x, eh0, el0); bf16_split(e2.y, eh1, el1);
                *(uint32_t*)(smem + OFF_A1 + a1_off(r, 32 + lane)) = pack2(eh0, eh1);
                *(uint32_t*)(smem + OFF_A1 + a1_off(r, 80 + lane)) = pack2(el0, el1);
            }
            float2 av = ((const float2*)(g_A + (size_t)src * 64))[lane];
            float2 bv = ((const float2*)(g_B + (size_t)dst * 64))[lane];
            base_s[r * 68 + 2 * lane]     = av.x + bv.x;
            base_s[r * 68 + 2 * lane + 1] = av.y + bv.y;
        }
        __syncthreads();

        // ---------------- L1 GEMM: 16 rows x 16 cols per warp ----------------
        float d[2][4] = {};
        #pragma unroll
        for (int s = 0; s < 18; s++) {
            int aks = (s < 12) ? s : s - 12;
            int bks = (s < 6) ? s : s - 6;
            uint4 A = *(const uint4*)(smem + OFF_A1 + ((rowgrp * 12 + aks) << 9) + lane * 16);
            #pragma unroll
            for (int nt = 0; nt < 2; nt++) {
                int ntg = npair * 2 + nt;
                uint2 B = *(const uint2*)(smem + OFF_B1 + ((ntg * 12 + bks) << 8) + lane * 8);
                hmma(d[nt], A, B);
            }
        }

        // ---------------- epilogue 1: +base, relu, split -> A2 ----------------
        {
            int r0 = rowgrp * 16 + (lane >> 2);
            #pragma unroll
            for (int nt = 0; nt < 2; nt++) {
                int c0 = npair * 16 + nt * 8 + 2 * q;
                float v00 = fmaxf(d[nt][0] + base_s[r0 * 68 + c0], 0.f);
                float v01 = fmaxf(d[nt][1] + base_s[r0 * 68 + c0 + 1], 0.f);
                float v10 = fmaxf(d[nt][2] + base_s[(r0 + 8) * 68 + c0], 0.f);
                float v11 = fmaxf(d[nt][3] + base_s[(r0 + 8) * 68 + c0 + 1], 0.f);
                float h00, l00, h01, l01, h10, l10, h11, l11;
                bf16_split(v00, h00, l00); bf16_split(v01, h01, l01);
                bf16_split(v10, h10, l10); bf16_split(v11, h11, l11);
                int c2 = c0 >> 1;
                *(uint32_t*)(smem + OFF_A2 + a2_off(r0,     c2))      = pack2(h00, h01);
                *(uint32_t*)(smem + OFF_A2 + a2_off(r0 + 8, c2))      = pack2(h10, h11);
                *(uint32_t*)(smem + OFF_A2 + a2_off(r0,     c2 + 32)) = pack2(l00, l01);
                *(uint32_t*)(smem + OFF_A2 + a2_off(r0 + 8, c2 + 32)) = pack2(l10, l11);
            }
        }
        __syncthreads();

        // ---------------- L2 GEMM: 16 rows x 8 cols per warp ----------------
        float e2a[4] = {};
        #pragma unroll
        for (int s = 0; s < 12; s++) {
            int aks = (s < 8) ? s : s - 8;
            int bks = (s < 4) ? s : s - 4;
            uint4 A = *(const uint4*)(smem + OFF_A2 + ((rowgrp * 8 + aks) << 9) + lane * 16);
            uint2 B = *(const uint2*)(smem + OFF_B2 + ((npair * 8 + bks) << 8) + lane * 8);
            hmma(e2a, A, B);
        }

        // ---------------- epilogue 2: +cb2, relu, dot cw3, reduce ------------
        {
            int c0 = npair * 8 + 2 * q;
            float w0 = cw3s[c0], w1 = cw3s[c0 + 1];
            float b0 = cb2s[c0], b1 = cb2s[c0 + 1];
            float p0 = fmaxf(e2a[0] + b0, 0.f) * w0 + fmaxf(e2a[1] + b1, 0.f) * w1;
            float p1 = fmaxf(e2a[2] + b0, 0.f) * w0 + fmaxf(e2a[3] + b1, 0.f) * w1;
            p0 += __shfl_xor_sync(0xffffffffu, p0, 1);
            p0 += __shfl_xor_sync(0xffffffffu, p0, 2);
            p1 += __shfl_xor_sync(0xffffffffu, p1, 1);
            p1 += __shfl_xor_sync(0xffffffffu, p1, 2);
            if (q == 0) {
                int r0 = rowgrp * 16 + (lane >> 2);
                atomicAdd(&log_s[r0], p0);
                atomicAdd(&log_s[r0 + 8], p1);
            }
        }
        __syncthreads();

        if (tid < 32) {
            out[e0 + tid] = log_s[tid] + cb3v;
            log_s[tid] = 0.f;
        }
    }
}

// ---------------- launch ----------------
extern "C" void kernel_launch(void* const* d_in, const int* in_sizes, int n_in,
                              void* d_out, int out_size)
{
    const float* x   = (const float*)d_in[0];
    const void*  ei  = (const void*)d_in[1];
    const float* ea  = (const float*)d_in[2];
    const float* wl0 = (const float*)d_in[3];
    const float* wr0 = (const float*)d_in[4];
    const float* b0  = (const float*)d_in[5];
    const float* g0  = (const float*)d_in[6];
    const float* bb0 = (const float*)d_in[7];
    const float* wl1 = (const float*)d_in[8];
    const float* wr1 = (const float*)d_in[9];
    const float* b1  = (const float*)d_in[10];
    const float* g1  = (const float*)d_in[11];
    const float* bb1 = (const float*)d_in[12];
    const float* cw1 = (const float*)d_in[13];
    const float* cb1 = (const float*)d_in[14];
    const float* cw2 = (const float*)d_in[15];
    const float* cb2 = (const float*)d_in[16];
    const float* cw3 = (const float*)d_in[17];
    const float* cb3 = (const float*)d_in[18];
    float* out = (float*)d_out;

    const int SCAN_BLOCKS = (N_NODES + 1023) / 1024;  // 98

    detect_kernel<<<1, 32>>>(ei);
    hist_kernel<<<(N_EDGES + 255) / 256, 256>>>(ei);
    scan1_kernel<<<SCAN_BLOCKS, 1024>>>();
    scan2_kernel<<<1, 128>>>(SCAN_BLOCKS);
    scan3_kernel<<<(N_NODES + 255) / 256, 256>>>();
    fill_kernel<<<(N_EDGES + 255) / 256, 256>>>(ei);

    sage_kernel<<<1480, 128>>>(x, 0, wl0, wr0, b0, g0, bb0);
    sage_kernel<<<1480, 128>>>(x, 1, wl1, wr1, b1, g1, bb1);
    node_pre_kernel<<<1480, 128>>>(cw1, cb1);

    cudaFuncSetAttribute(edge_mma_kernel,
                         cudaFuncAttributeMaxDynamicSharedMemorySize, EDGE_SMEM_TOTAL);
    edge_mma_kernel<<<444, 256, EDGE_SMEM_TOTAL>>>(
        ei, ea, cw1, cw2, cb2, cw3, cb3, out);
}